// round 5
// baseline (speedup 1.0000x reference)
#include <cuda_runtime.h>
#include <cuda_bf16.h>

#define BS    4
#define NH    8
#define SEQ   2048
#define DK    64
#define NP    129
#define TI    4          // i-rows per block
#define PSTR2 130        // float2 stride for swT rows
#define HSTR  12         // floats per position in table (8 heads + pad, 16B-aligned)
#define NT    256

// smem layout:
//   swT : float2 [32][PSTR2]        33280 B   (w transposed, k-major)
//   sq  : float  [TI][NH][DK]        8192 B
//   t   : float  [TI][NP pad][HSTR] 24576 B   (position-major, heads innermost)
#define SWT_BYTES (32 * PSTR2 * 8)
#define SQ_BYTES  (TI * NH * DK * 4)
#define T_FLOATS_PER_IL (128 * HSTR + 16)     // 129 positions, pad to 16-float mult
#define T_BYTES   (TI * T_FLOATS_PER_IL * 4)  // 4*1552*4 = 24832
#define SMEM_BYTES (SWT_BYTES + SQ_BYTES + T_BYTES)

__device__ __forceinline__ unsigned long long fma2(unsigned long long a,
                                                   unsigned long long b,
                                                   unsigned long long c) {
    unsigned long long d;
    asm("fma.rn.f32x2 %0, %1, %2, %3;" : "=l"(d) : "l"(a), "l"(b), "l"(c));
    return d;
}

__global__ void __launch_bounds__(NT, 3)
fused_kernel(const float* __restrict__ q,
             const int*   __restrict__ dist,
             const float* __restrict__ w,
             float*       __restrict__ out) {
    extern __shared__ char smem_raw[];
    float2* swT = reinterpret_cast<float2*>(smem_raw);                    // [32][PSTR2]
    float*  sq  = reinterpret_cast<float*>(smem_raw + SWT_BYTES);         // [TI][NH][DK]
    float*  tsm = reinterpret_cast<float*>(smem_raw + SWT_BYTES + SQ_BYTES);

    const int tid = threadIdx.x;
    const int bi  = blockIdx.x;              // 0..2047
    const int b   = bi >> 9;                 // 512 blocks per batch
    const int i0  = (bi & 511) * TI;

    // ---- load w transposed: swT[k2][p] = (w[p][2k2], w[p][2k2+1]); pad with 0
    {
        const float2* w2 = reinterpret_cast<const float2*>(w);
        for (int idx = tid; idx < 32 * PSTR2; idx += NT) {
            const int k2 = idx / PSTR2;
            const int p  = idx - k2 * PSTR2;
            float2 v = make_float2(0.f, 0.f);
            if (p < NP) v = w2[p * 32 + k2];
            swT[idx] = v;
        }
    }
    // ---- load q tile: sq[r][h][k]
    {
        const float4* q4 = reinterpret_cast<const float4*>(q);
        float4* sq4 = reinterpret_cast<float4*>(sq);
        for (int idx = tid; idx < TI * NH * 16; idx += NT) {
            const int r  = idx >> 7;             // /128
            const int h  = (idx >> 4) & 7;
            const int kq = idx & 15;
            sq4[idx] = q4[(((size_t)(b * NH + h) * SEQ) + i0 + r) * 16 + kq];
        }
    }
    __syncthreads();

    // ---- projection: warp-pair per i-row, 4 heads per warp.
    //      thread = (r = warp>>1, hh = (warp&1)*4, p0 = lane);
    //      covers h in [hh,hh+4), p in {p0, p0+32, p0+64, p0+96, 128}
    //      table stored position-major: tsm[r][p][h]
    {
        const int warp = tid >> 5, lane = tid & 31;
        const int r  = warp >> 1;
        const int hh = (warp & 1) * 4;
        const float2* sqf2 = reinterpret_cast<const float2*>(sq) + (r * NH + hh) * 32;

        unsigned long long acc[4][5];
#pragma unroll
        for (int hl = 0; hl < 4; hl++)
#pragma unroll
            for (int u = 0; u < 5; u++) acc[hl][u] = 0ULL;

#pragma unroll 8
        for (int k2 = 0; k2 < 32; k2++) {
            const float2* wrow = swT + k2 * PSTR2;
            unsigned long long wv[5];
#pragma unroll
            for (int u = 0; u < 4; u++)
                wv[u] = *reinterpret_cast<const unsigned long long*>(wrow + lane + 32 * u);
            wv[4] = *reinterpret_cast<const unsigned long long*>(wrow + 128);
#pragma unroll
            for (int hl = 0; hl < 4; hl++) {
                unsigned long long qv = *reinterpret_cast<const unsigned long long*>(
                                            sqf2 + hl * 32 + k2);
#pragma unroll
                for (int u = 0; u < 5; u++)
                    acc[hl][u] = fma2(qv, wv[u], acc[hl][u]);
            }
        }

        float* tr = tsm + r * T_FLOATS_PER_IL;
#pragma unroll
        for (int hl = 0; hl < 4; hl++) {
#pragma unroll
            for (int u = 0; u < 4; u++) {
                float2 v = *reinterpret_cast<float2*>(&acc[hl][u]);
                tr[(lane + 32 * u) * HSTR + hh + hl] = v.x + v.y;
            }
            if (lane == 0) {
                float2 v = *reinterpret_cast<float2*>(&acc[hl][4]);
                tr[128 * HSTR + hh + hl] = v.x + v.y;
            }
        }
    }
    __syncthreads();

    // ---- gather: out[b,h,i,j] = t[i-i0][min(dist,128)][h]
    {
        // hoist all dist loads (MLP = 8)
        int4 dv[TI * 2];
#pragma unroll
        for (int il = 0; il < TI; il++) {
            const int4* drow = reinterpret_cast<const int4*>(
                dist + ((size_t)(b * SEQ + i0 + il)) * SEQ);
#pragma unroll
            for (int rep = 0; rep < 2; rep++)
                dv[il * 2 + rep] = __ldcs(&drow[rep * NT + tid]);
        }

#pragma unroll
        for (int il = 0; il < TI; il++) {
            const float4* ti4 = reinterpret_cast<const float4*>(
                tsm + il * T_FLOATS_PER_IL);          // 3 float4 per position
#pragma unroll
            for (int rep = 0; rep < 2; rep++) {
                const int jv = rep * NT + tid;
                const int4 d = dv[il * 2 + rep];
                const int pa = min(d.x, 128);
                const int pb = min(d.y, 128);
                const int pc = min(d.z, 128);
                const int pd = min(d.w, 128);

                // 8 LDS.128: 4 positions x (heads 0-3, heads 4-7)
                float4 la0 = ti4[pa * 3 + 0], la1 = ti4[pa * 3 + 1];
                float4 lb0 = ti4[pb * 3 + 0], lb1 = ti4[pb * 3 + 1];
                float4 lc0 = ti4[pc * 3 + 0], lc1 = ti4[pc * 3 + 1];
                float4 ld0 = ti4[pd * 3 + 0], ld1 = ti4[pd * 3 + 1];

                const float va[8] = {la0.x, la0.y, la0.z, la0.w, la1.x, la1.y, la1.z, la1.w};
                const float vb[8] = {lb0.x, lb0.y, lb0.z, lb0.w, lb1.x, lb1.y, lb1.z, lb1.w};
                const float vc[8] = {lc0.x, lc0.y, lc0.z, lc0.w, lc1.x, lc1.y, lc1.z, lc1.w};
                const float vd[8] = {ld0.x, ld0.y, ld0.z, ld0.w, ld1.x, ld1.y, ld1.z, ld1.w};

#pragma unroll
                for (int h = 0; h < NH; h++) {
                    float4 v = make_float4(va[h], vb[h], vc[h], vd[h]);
                    float4* op = reinterpret_cast<float4*>(
                        out + (((size_t)(b * NH + h) * SEQ) + i0 + il) * SEQ);
                    __stcs(&op[jv], v);
                }
            }
        }
    }
}

extern "C" void kernel_launch(void* const* d_in, const int* in_sizes, int n_in,
                              void* d_out, int out_size) {
    const float* q    = (const float*)d_in[0];
    const int*   dist = (const int*)  d_in[1];
    const float* w    = (const float*)d_in[2];
    float*       out  = (float*)d_out;

    cudaFuncSetAttribute(fused_kernel,
                         cudaFuncAttributeMaxDynamicSharedMemorySize, SMEM_BYTES);

    fused_kernel<<<BS * (SEQ / TI), NT, SMEM_BYTES>>>(q, dist, w, out);
}